// round 3
// baseline (speedup 1.0000x reference)
#include <cuda_runtime.h>

#define NN 100000
#define EE 600000
#define IND 12
#define HD  128
#define NL  3
#define BNEPS 1e-5f

// ---------------- device scratch (static, no allocation) ----------------
// Only TWO N x H buffers: the GEMM writes in-place over the msg buffer
// (legal: each row-block's output depends only on that block's own rows).
__device__ float g_buf0[NN * HD];
__device__ float g_buf1[NN * HD];
__device__ int   g_src[EE];
__device__ int   g_dst[EE];
__device__ int   g_deg[NN];
__device__ float g_invdeg[NN];
__device__ float g_sum[HD];
__device__ float g_sqsum[HD];
__device__ float g_scale[HD];
__device__ float g_shift[HD];
__device__ int   g_is64;

__device__ __forceinline__ float* selbuf(int s) { return s ? g_buf1 : g_buf0; }

// ---------------- dtype detection for edge_index (int32 vs int64) -------
__global__ void detect_dtype_kernel(const void* p) {
    const int* pi = (const int*)p;
    int nz = 0;
    // int64 values < 2^31: every odd 32-bit word is 0. int32 random: not.
    for (int k = threadIdx.x; k < 256; k += blockDim.x)
        nz |= (pi[2 * k + 1] != 0);
    nz = __syncthreads_or(nz);
    if (threadIdx.x == 0) g_is64 = nz ? 0 : 1;
}

__global__ void extract_edges_kernel(const void* p) {
    int i = blockIdx.x * blockDim.x + threadIdx.x;
    if (i >= 2 * EE) return;
    int v;
    if (g_is64) v = (int)((const long long*)p)[i];
    else        v = ((const int*)p)[i];
    if (i < EE) g_src[i] = v;
    else        g_dst[i - EE] = v;
}

// ---------------- degree ----------------
__global__ void zero_deg_kernel() {
    int i = blockIdx.x * blockDim.x + threadIdx.x;
    if (i < NN) g_deg[i] = 0;
}
__global__ void count_deg_kernel() {
    int e = blockIdx.x * blockDim.x + threadIdx.x;
    if (e < EE) atomicAdd(&g_deg[g_dst[e]], 1);
}
__global__ void calc_invdeg_kernel() {
    int i = blockIdx.x * blockDim.x + threadIdx.x;
    if (i < NN) g_invdeg[i] = 1.0f / fmaxf((float)g_deg[i], 1.0f);
}

// ---------------- embedding: h = F @ emb_W + emb_b  -> buf0 -------------
__global__ void embed_kernel(const float* __restrict__ F,
                             const float* __restrict__ W,
                             const float* __restrict__ b) {
    __shared__ float Ws[IND * HD];
    for (int i = threadIdx.x; i < IND * HD; i += blockDim.x) Ws[i] = W[i];
    __syncthreads();
    float* Hout = g_buf0;
    int c = threadIdx.x;  // 128 threads
    float bc = b[c];
    for (int n = blockIdx.x; n < NN; n += gridDim.x) {
        float acc = bc;
#pragma unroll
        for (int k = 0; k < IND; k++)
            acc += F[n * IND + k] * Ws[k * HD + c];
        Hout[n * HD + c] = acc;
    }
}

// ---------------- zero msg buffer + BN partial sums ----------------
__global__ void zero_msg_stats_kernel(int msgsel) {
    float* msg = selbuf(msgsel);
    int i = blockIdx.x * blockDim.x + threadIdx.x;
    int total4 = NN * HD / 4;
    if (i < total4) ((float4*)msg)[i] = make_float4(0.f, 0.f, 0.f, 0.f);
    if (blockIdx.x == 0 && threadIdx.x < HD) {
        g_sum[threadIdx.x] = 0.f;
        g_sqsum[threadIdx.x] = 0.f;
    }
}

// ---------------- edge scatter: msg[dst] += h[src] (vector RED) --------
__global__ void scatter_kernel(int hsel) {
    const float* h = selbuf(hsel);
    float* msg = selbuf(hsel ^ 1);
    int gid = blockIdx.x * blockDim.x + threadIdx.x;
    int e = gid >> 5;
    if (e >= EE) return;
    int lane = gid & 31;
    int s = g_src[e];
    int d = g_dst[e];
    float4 v = __ldg((const float4*)(h + (size_t)s * HD) + lane);
    float* dstp = msg + (size_t)d * HD + lane * 4;
    asm volatile("red.global.add.v4.f32 [%0], {%1, %2, %3, %4};"
                 :: "l"(dstp), "f"(v.x), "f"(v.y), "f"(v.z), "f"(v.w)
                 : "memory");
}

// ---------------- fused dual GEMM (IN-PLACE over msg buffer):
//   C = h @ Wself + (msg * invdeg) @ Wneigh + bias,  C overwrites msg.
//   Safe: row-block b reads only rows [row0,row0+128) of h and msg (clamp
//   stays in-block), all global reads precede the final __syncthreads(),
//   writes follow it; no cross-block row sharing.
#define BM 128
#define BK 16
__global__ void __launch_bounds__(256, 2)
gemm_layer_kernel(int hsel,
                  const float* __restrict__ Ws,
                  const float* __restrict__ Wn,
                  const float* __restrict__ bias) {
    __shared__ float As[BK][BM];
    __shared__ float Bs[BK][HD];
    const float* A1 = selbuf(hsel);
    float* Msg = selbuf(hsel ^ 1);
    float* C = Msg;  // in-place
    const int nrows = NN;
    int tid = threadIdx.x;
    int tx = tid & 15, ty = tid >> 4;
    int row0 = blockIdx.x * BM;
    float acc[8][8];
#pragma unroll
    for (int i = 0; i < 8; i++)
#pragma unroll
        for (int j = 0; j < 8; j++) acc[i][j] = 0.f;

    for (int pass = 0; pass < 2; ++pass) {
        const float* A = pass ? Msg : A1;
        const float* W = pass ? Wn : Ws;
        for (int k0 = 0; k0 < HD; k0 += BK) {
            // A tile: 128 rows x 16 cols = 512 float4 loads / 256 threads
#pragma unroll
            for (int q = 0; q < 2; q++) {
                int idx = tid * 2 + q;          // 0..511
                int m = idx >> 2;               // row in tile
                int kk = (idx & 3) * 4;         // col in tile
                int row = row0 + m;
                int rc = row < nrows ? row : nrows - 1;
                float4 v = __ldg((const float4*)(A + (size_t)rc * HD + k0 + kk));
                float sc = pass ? g_invdeg[rc] : 1.0f;
                As[kk + 0][m] = v.x * sc;
                As[kk + 1][m] = v.y * sc;
                As[kk + 2][m] = v.z * sc;
                As[kk + 3][m] = v.w * sc;
            }
            // W tile: 16 rows x 128 cols
#pragma unroll
            for (int q = 0; q < 2; q++) {
                int idx = tid * 2 + q;          // float4 id 0..511
                int kk = idx >> 5;              // row 0..15
                int c4 = idx & 31;              // float4 col
                float4 v = __ldg((const float4*)(W + (size_t)(k0 + kk) * HD + c4 * 4));
                *(float4*)&Bs[kk][c4 * 4] = v;
            }
            __syncthreads();
#pragma unroll
            for (int kk = 0; kk < BK; kk++) {
                float ra[8], rb[8];
#pragma unroll
                for (int i = 0; i < 8; i++) ra[i] = As[kk][ty * 8 + i];
#pragma unroll
                for (int j = 0; j < 8; j++) rb[j] = Bs[kk][tx * 8 + j];
#pragma unroll
                for (int i = 0; i < 8; i++)
#pragma unroll
                    for (int j = 0; j < 8; j++) acc[i][j] += ra[i] * rb[j];
            }
            __syncthreads();
        }
    }
#pragma unroll
    for (int i = 0; i < 8; i++) {
        int row = row0 + ty * 8 + i;
        if (row < nrows) {
#pragma unroll
            for (int j = 0; j < 8; j += 4) {
                int c = tx * 8 + j;
                float4 o;
                o.x = acc[i][j + 0] + bias[c + 0];
                o.y = acc[i][j + 1] + bias[c + 1];
                o.z = acc[i][j + 2] + bias[c + 2];
                o.w = acc[i][j + 3] + bias[c + 3];
                *(float4*)(C + (size_t)row * HD + c) = o;
            }
        }
    }
}

// ---------------- BatchNorm statistics ----------------
__global__ void bn_stats_kernel(int sel) {
    const float* X = selbuf(sel);
    int c = threadIdx.x;  // 128
    float s = 0.f, s2 = 0.f;
    for (int r = blockIdx.x; r < NN; r += gridDim.x) {
        float v = X[(size_t)r * HD + c];
        s += v;
        s2 += v * v;
    }
    atomicAdd(&g_sum[c], s);
    atomicAdd(&g_sqsum[c], s2);
}

__global__ void bn_finalize_kernel(const float* __restrict__ gamma,
                                   const float* __restrict__ beta) {
    int c = threadIdx.x;
    float mu = g_sum[c] * (1.0f / NN);
    float var = g_sqsum[c] * (1.0f / NN) - mu * mu;
    float r = rsqrtf(var + BNEPS);
    float a = gamma[c] * r;
    g_scale[c] = a;
    g_shift[c] = beta[c] - mu * a;
}

// ---------------- BN apply + ReLU + (residual) ----------------
// X = new activations (in msg buffer, sel = h^1); residual source = old h.
__global__ void bn_apply_kernel(int sel, int addres) {
    float* X = selbuf(sel);
    const float* Res = selbuf(sel ^ 1);  // layer input = residual source
    int i = blockIdx.x * blockDim.x + threadIdx.x;
    int total4 = NN * HD / 4;
    if (i >= total4) return;
    int c = (i & 31) * 4;
    float4 v = ((float4*)X)[i];
    v.x = fmaxf(v.x * g_scale[c + 0] + g_shift[c + 0], 0.f);
    v.y = fmaxf(v.y * g_scale[c + 1] + g_shift[c + 1], 0.f);
    v.z = fmaxf(v.z * g_scale[c + 2] + g_shift[c + 2], 0.f);
    v.w = fmaxf(v.w * g_scale[c + 3] + g_shift[c + 3], 0.f);
    if (addres) {
        float4 r = ((const float4*)Res)[i];
        v.x += r.x; v.y += r.y; v.z += r.z; v.w += r.w;
    }
    ((float4*)X)[i] = v;
}

// ---------------- MLP head: out = relu(h@W1+b1)@W2+b2 ----------------
__global__ void head_kernel(int sel,
                            const float* __restrict__ W1,
                            const float* __restrict__ b1,
                            const float* __restrict__ W2,
                            const float* __restrict__ b2,
                            float* __restrict__ out) {
    const float* Hin = selbuf(sel);
    __shared__ float W1s[HD * 64];
    __shared__ float W2s[64 * 2];
    __shared__ float b1s[64];
    for (int i = threadIdx.x; i < HD * 64; i += blockDim.x) W1s[i] = W1[i];
    if (threadIdx.x < 128) W2s[threadIdx.x] = W2[threadIdx.x];
    if (threadIdx.x < 64) b1s[threadIdx.x] = b1[threadIdx.x];
    __syncthreads();
    int lane = threadIdx.x & 31;
    int w = threadIdx.x >> 5;
    int wpg = gridDim.x * (blockDim.x >> 5);
    float b20 = b2[0], b21 = b2[1];
    for (int n = blockIdx.x * (blockDim.x >> 5) + w; n < NN; n += wpg) {
        float4 h4 = __ldg((const float4*)(Hin + (size_t)n * HD) + lane);
        float hv[4] = {h4.x, h4.y, h4.z, h4.w};
        float a0 = b1s[lane], a1 = b1s[lane + 32];
#pragma unroll
        for (int k = 0; k < HD; k++) {
            float v = __shfl_sync(0xffffffffu, hv[k & 3], k >> 2);
            a0 += v * W1s[k * 64 + lane];
            a1 += v * W1s[k * 64 + lane + 32];
        }
        a0 = fmaxf(a0, 0.f);
        a1 = fmaxf(a1, 0.f);
        float o0 = a0 * W2s[lane * 2 + 0] + a1 * W2s[(lane + 32) * 2 + 0];
        float o1 = a0 * W2s[lane * 2 + 1] + a1 * W2s[(lane + 32) * 2 + 1];
#pragma unroll
        for (int off = 16; off; off >>= 1) {
            o0 += __shfl_xor_sync(0xffffffffu, o0, off);
            o1 += __shfl_xor_sync(0xffffffffu, o1, off);
        }
        if (lane == 0) {
            out[n * 2 + 0] = o0 + b20;
            out[n * 2 + 1] = o1 + b21;
        }
    }
}

// ---------------- launch (kernel launches ONLY — no other CUDA API) ----
extern "C" void kernel_launch(void* const* d_in, const int* in_sizes, int n_in,
                              void* d_out, int out_size) {
    const float* features = (const float*)d_in[0];
    const void*  edge     = d_in[1];
    const float* emb_W    = (const float*)d_in[2];
    const float* emb_b    = (const float*)d_in[3];
    const float* Wself    = (const float*)d_in[4];
    const float* Wneigh   = (const float*)d_in[5];
    const float* conv_b   = (const float*)d_in[6];
    const float* gamma    = (const float*)d_in[7];
    const float* beta     = (const float*)d_in[8];
    const float* W1       = (const float*)d_in[9];
    const float* b1       = (const float*)d_in[10];
    const float* W2       = (const float*)d_in[11];
    const float* b2       = (const float*)d_in[12];
    float* out = (float*)d_out;

    detect_dtype_kernel<<<1, 128>>>(edge);
    extract_edges_kernel<<<(2 * EE + 255) / 256, 256>>>(edge);
    zero_deg_kernel<<<(NN + 255) / 256, 256>>>();
    count_deg_kernel<<<(EE + 255) / 256, 256>>>();
    calc_invdeg_kernel<<<(NN + 255) / 256, 256>>>();
    embed_kernel<<<2048, 128>>>(features, emb_W, emb_b);  // h -> buf0

    int h = 0;  // current h buffer selector; msg buffer is h^1
    for (int i = 0; i < NL; i++) {
        zero_msg_stats_kernel<<<(NN * HD / 4 + 255) / 256, 256>>>(h ^ 1);
        scatter_kernel<<<(EE * 32 + 255) / 256, 256>>>(h);
        gemm_layer_kernel<<<(NN + BM - 1) / BM, 256>>>(
            h, Wself + (size_t)i * HD * HD, Wneigh + (size_t)i * HD * HD,
            conv_b + i * HD);                        // writes into h^1
        bn_stats_kernel<<<512, 128>>>(h ^ 1);
        bn_finalize_kernel<<<1, HD>>>(gamma + i * HD, beta + i * HD);
        bn_apply_kernel<<<(NN * HD / 4 + 255) / 256, 256>>>(h ^ 1, i > 0);
        h ^= 1;
    }
    head_kernel<<<1024, 256>>>(h, W1, b1, W2, b2, out);
}

// round 5
// speedup vs baseline: 1.3437x; 1.3437x over previous
#include <cuda_runtime.h>
#include <mma.h>

using namespace nvcuda;

#define NN 100000
#define EE 600000
#define IND 12
#define HD  128
#define NL  3
#define BNEPS 1e-5f

// ---------------- device scratch (static, no allocation) ----------------
__device__ float g_buf0[NN * HD];
__device__ float g_buf1[NN * HD];
__device__ int   g_src[EE];
__device__ int   g_dst[EE];
__device__ int   g_deg[NN];
__device__ float g_invdeg[NN];
__device__ float g_sum[HD];
__device__ float g_sqsum[HD];
__device__ float g_scale[HD];
__device__ float g_shift[HD];
__device__ int   g_is64;

__device__ __forceinline__ float* selbuf(int s) { return s ? g_buf1 : g_buf0; }

// ---------------- dtype detection for edge_index (int32 vs int64) -------
__global__ void detect_dtype_kernel(const void* p) {
    const int* pi = (const int*)p;
    int nz = 0;
    for (int k = threadIdx.x; k < 256; k += blockDim.x)
        nz |= (pi[2 * k + 1] != 0);
    nz = __syncthreads_or(nz);
    if (threadIdx.x == 0) g_is64 = nz ? 0 : 1;
}

__global__ void extract_edges_kernel(const void* p) {
    int i = blockIdx.x * blockDim.x + threadIdx.x;
    if (i >= 2 * EE) return;
    int v;
    if (g_is64) v = (int)((const long long*)p)[i];
    else        v = ((const int*)p)[i];
    if (i < EE) g_src[i] = v;
    else        g_dst[i - EE] = v;
}

// ---------------- degree ----------------
__global__ void zero_deg_kernel() {
    int i = blockIdx.x * blockDim.x + threadIdx.x;
    if (i < NN) g_deg[i] = 0;
}
__global__ void count_deg_kernel() {
    int e = blockIdx.x * blockDim.x + threadIdx.x;
    if (e < EE) atomicAdd(&g_deg[g_dst[e]], 1);
}
__global__ void calc_invdeg_kernel() {
    int i = blockIdx.x * blockDim.x + threadIdx.x;
    if (i < NN) g_invdeg[i] = 1.0f / fmaxf((float)g_deg[i], 1.0f);
}

// ---------------- embedding: h = F @ emb_W + emb_b  -> buf0 -------------
__global__ void embed_kernel(const float* __restrict__ F,
                             const float* __restrict__ W,
                             const float* __restrict__ b) {
    __shared__ float Ws[IND * HD];
    for (int i = threadIdx.x; i < IND * HD; i += blockDim.x) Ws[i] = W[i];
    __syncthreads();
    float* Hout = g_buf0;
    int c = threadIdx.x;  // 128 threads
    float bc = b[c];
    for (int n = blockIdx.x; n < NN; n += gridDim.x) {
        float acc = bc;
#pragma unroll
        for (int k = 0; k < IND; k++)
            acc += F[n * IND + k] * Ws[k * HD + c];
        Hout[n * HD + c] = acc;
    }
}

// ---------------- zero msg buffer + BN partial sums ----------------
__global__ void zero_msg_stats_kernel(int msgsel) {
    float* msg = selbuf(msgsel);
    int i = blockIdx.x * blockDim.x + threadIdx.x;
    int total4 = NN * HD / 4;
    if (i < total4) ((float4*)msg)[i] = make_float4(0.f, 0.f, 0.f, 0.f);
    if (blockIdx.x == 0 && threadIdx.x < HD) {
        g_sum[threadIdx.x] = 0.f;
        g_sqsum[threadIdx.x] = 0.f;
    }
}

// ---------------- edge scatter: msg[dst] += h[src] (vector RED) --------
__global__ void scatter_kernel(int hsel) {
    const float* h = selbuf(hsel);
    float* msg = selbuf(hsel ^ 1);
    int gid = blockIdx.x * blockDim.x + threadIdx.x;
    int e = gid >> 5;
    if (e >= EE) return;
    int lane = gid & 31;
    int s = g_src[e];
    int d = g_dst[e];
    float4 v = __ldg((const float4*)(h + (size_t)s * HD) + lane);
    float* dstp = msg + (size_t)d * HD + lane * 4;
    asm volatile("red.global.add.v4.f32 [%0], {%1, %2, %3, %4};"
                 :: "l"(dstp), "f"(v.x), "f"(v.y), "f"(v.z), "f"(v.w)
                 : "memory");
}

// ---------------- fused dual GEMM (tf32 tensor cores, in-place) --------
//   C = h @ Wself + (msg * invdeg) @ Wneigh + bias,  C overwrites msg.
//   BN column statistics fused into the epilogue.
//   NOTE: all wmma ldm values MUST be multiples of 4 floats (16 bytes).
#define BM 128
#define BK 16
#define ALD (BK + 4)     // 20 floats = 80 B, x16 OK
#define BLD (HD + 4)     // 132 floats, x16 OK
#define WTLD 20          // was 17 (68 B, ILLEGAL for wmma); 20 = 80 B OK
__global__ void __launch_bounds__(256)
gemm_layer_kernel(int hsel,
                  const float* __restrict__ Wsp,
                  const float* __restrict__ Wnp,
                  const float* __restrict__ bias) {
    __shared__ float As[BM * ALD];
    __shared__ float Bs[BK * BLD];
    __shared__ float wtile[8][16 * WTLD];
    __shared__ float colsum[HD], colsq[HD];

    const float* A1 = selbuf(hsel);
    float* Msg = selbuf(hsel ^ 1);
    float* C = Msg;  // in-place
    const int nrows = NN;
    int tid = threadIdx.x;
    int w = tid >> 5, lane = tid & 31;
    int wm = w & 3, wn = w >> 2;       // warp grid 4(M) x 2(N)
    int row0 = blockIdx.x * BM;

    if (tid < HD) { colsum[tid] = 0.f; colsq[tid] = 0.f; }

    wmma::fragment<wmma::accumulator, 16, 16, 8, float> acc[2][4];
#pragma unroll
    for (int i = 0; i < 2; i++)
#pragma unroll
        for (int j = 0; j < 4; j++) wmma::fill_fragment(acc[i][j], 0.f);

    for (int pass = 0; pass < 2; ++pass) {
        const float* A = pass ? Msg : A1;
        const float* W = pass ? Wnp : Wsp;
        for (int k0 = 0; k0 < HD; k0 += BK) {
            __syncthreads();
            // A tile: 128 rows x 16 cols (512 float4 loads / 256 threads)
#pragma unroll
            for (int q = 0; q < 2; q++) {
                int idx = tid * 2 + q;          // 0..511
                int m = idx >> 2;               // row in tile
                int kk = (idx & 3) * 4;         // col in tile
                int row = row0 + m;
                int rc = row < nrows ? row : nrows - 1;
                float4 v = __ldg((const float4*)(A + (size_t)rc * HD + k0 + kk));
                float sc = pass ? g_invdeg[rc] : 1.0f;
                As[m * ALD + kk + 0] = v.x * sc;
                As[m * ALD + kk + 1] = v.y * sc;
                As[m * ALD + kk + 2] = v.z * sc;
                As[m * ALD + kk + 3] = v.w * sc;
            }
            // W tile: 16 rows x 128 cols
#pragma unroll
            for (int q = 0; q < 2; q++) {
                int idx = tid * 2 + q;
                int kk = idx >> 5;
                int c4 = idx & 31;
                float4 v = __ldg((const float4*)(W + (size_t)(k0 + kk) * HD + c4 * 4));
                Bs[kk * BLD + c4 * 4 + 0] = v.x;
                Bs[kk * BLD + c4 * 4 + 1] = v.y;
                Bs[kk * BLD + c4 * 4 + 2] = v.z;
                Bs[kk * BLD + c4 * 4 + 3] = v.w;
            }
            __syncthreads();
#pragma unroll
            for (int ks = 0; ks < BK; ks += 8) {
                wmma::fragment<wmma::matrix_a, 16, 16, 8, wmma::precision::tf32, wmma::row_major> af[2];
                wmma::fragment<wmma::matrix_b, 16, 16, 8, wmma::precision::tf32, wmma::row_major> bf[4];
#pragma unroll
                for (int i = 0; i < 2; i++) {
                    wmma::load_matrix_sync(af[i], &As[(wm * 32 + i * 16) * ALD + ks], ALD);
#pragma unroll
                    for (int t = 0; t < af[i].num_elements; t++)
                        af[i].x[t] = wmma::__float_to_tf32(af[i].x[t]);
                }
#pragma unroll
                for (int j = 0; j < 4; j++) {
                    wmma::load_matrix_sync(bf[j], &Bs[ks * BLD + wn * 64 + j * 16], BLD);
#pragma unroll
                    for (int t = 0; t < bf[j].num_elements; t++)
                        bf[j].x[t] = wmma::__float_to_tf32(bf[j].x[t]);
                }
#pragma unroll
                for (int i = 0; i < 2; i++)
#pragma unroll
                    for (int j = 0; j < 4; j++)
                        wmma::mma_sync(acc[i][j], af[i], bf[j], acc[i][j]);
            }
        }
    }

    // Epilogue: bias add, bounds-checked store, fused BN column stats.
    float* wt = wtile[w];
    int cl = lane & 15;        // column within 16
    int rh = lane >> 4;        // row half (0/1)
#pragma unroll
    for (int i = 0; i < 2; i++) {
#pragma unroll
        for (int j = 0; j < 4; j++) {
            wmma::store_matrix_sync(wt, acc[i][j], WTLD, wmma::mem_row_major);
            __syncwarp();
            int gc = wn * 64 + j * 16 + cl;
            int rbase = row0 + wm * 32 + i * 16 + rh * 8;
            float bia = bias[gc];
            float s = 0.f, s2 = 0.f;
#pragma unroll
            for (int r = 0; r < 8; r++) {
                int gr = rbase + r;
                float v = wt[(rh * 8 + r) * WTLD + cl] + bia;
                if (gr < nrows) {
                    C[(size_t)gr * HD + gc] = v;
                    s += v;
                    s2 += v * v;
                }
            }
            s  += __shfl_down_sync(0xffffffffu, s, 16);
            s2 += __shfl_down_sync(0xffffffffu, s2, 16);
            if (lane < 16) {
                atomicAdd(&colsum[gc], s);
                atomicAdd(&colsq[gc], s2);
            }
            __syncwarp();
        }
    }
    __syncthreads();
    if (tid < HD) {
        atomicAdd(&g_sum[tid], colsum[tid]);
        atomicAdd(&g_sqsum[tid], colsq[tid]);
    }
}

// ---------------- BN finalize ----------------
__global__ void bn_finalize_kernel(const float* __restrict__ gamma,
                                   const float* __restrict__ beta) {
    int c = threadIdx.x;
    float mu = g_sum[c] * (1.0f / NN);
    float var = g_sqsum[c] * (1.0f / NN) - mu * mu;
    float r = rsqrtf(var + BNEPS);
    float a = gamma[c] * r;
    g_scale[c] = a;
    g_shift[c] = beta[c] - mu * a;
}

// ---------------- BN apply + ReLU + (residual) ----------------
__global__ void bn_apply_kernel(int sel, int addres) {
    float* X = selbuf(sel);
    const float* Res = selbuf(sel ^ 1);  // layer input = residual source
    int i = blockIdx.x * blockDim.x + threadIdx.x;
    int total4 = NN * HD / 4;
    if (i >= total4) return;
    int c = (i & 31) * 4;
    float4 v = ((float4*)X)[i];
    v.x = fmaxf(v.x * g_scale[c + 0] + g_shift[c + 0], 0.f);
    v.y = fmaxf(v.y * g_scale[c + 1] + g_shift[c + 1], 0.f);
    v.z = fmaxf(v.z * g_scale[c + 2] + g_shift[c + 2], 0.f);
    v.w = fmaxf(v.w * g_scale[c + 3] + g_shift[c + 3], 0.f);
    if (addres) {
        float4 r = ((const float4*)Res)[i];
        v.x += r.x; v.y += r.y; v.z += r.z; v.w += r.w;
    }
    ((float4*)X)[i] = v;
}

// ---------------- MLP head: out = relu(h@W1+b1)@W2+b2 ----------------
__global__ void head_kernel(int sel,
                            const float* __restrict__ W1,
                            const float* __restrict__ b1,
                            const float* __restrict__ W2,
                            const float* __restrict__ b2,
                            float* __restrict__ out) {
    const float* Hin = selbuf(sel);
    __shared__ float W1s[HD * 64];
    __shared__ float W2s[64 * 2];
    __shared__ float b1s[64];
    for (int i = threadIdx.x; i < HD * 64; i += blockDim.x) W1s[i] = W1[i];
    if (threadIdx.x < 128) W2s[threadIdx.x] = W2[threadIdx.x];
    if (threadIdx.x < 64) b1s[threadIdx.x] = b1[threadIdx.x];
    __syncthreads();
    int lane = threadIdx.x & 31;
    int w = threadIdx.x >> 5;
    int wpg = gridDim.x * (blockDim.x >> 5);
    float b20 = b2[0], b21 = b2[1];
    for (int n = blockIdx.x * (blockDim.x >> 5) + w; n < NN; n += wpg) {
        float4 h4 = __ldg((const float4*)(Hin + (size_t)n * HD) + lane);
        float hv[4] = {h4.x, h4.y, h4.z, h4.w};
        float a0 = b1s[lane], a1 = b1s[lane + 32];
#pragma unroll
        for (int k = 0; k < HD; k++) {
            float v = __shfl_sync(0xffffffffu, hv[k & 3], k >> 2);
            a0 += v * W1s[k * 64 + lane];
            a1 += v * W1s[k * 64 + lane + 32];
        }
        a0 = fmaxf(a0, 0.f);
        a1 = fmaxf(a1, 0.f);
        float o0 = a0 * W2s[lane * 2 + 0] + a1 * W2s[(lane + 32) * 2 + 0];
        float o1 = a0 * W2s[lane * 2 + 1] + a1 * W2s[(lane + 32) * 2 + 1];
#pragma unroll
        for (int off = 16; off; off >>= 1) {
            o0 += __shfl_xor_sync(0xffffffffu, o0, off);
            o1 += __shfl_xor_sync(0xffffffffu, o1, off);
        }
        if (lane == 0) {
            out[n * 2 + 0] = o0 + b20;
            out[n * 2 + 1] = o1 + b21;
        }
    }
}

// ---------------- launch (kernel launches ONLY) ----------------
extern "C" void kernel_launch(void* const* d_in, const int* in_sizes, int n_in,
                              void* d_out, int out_size) {
    const float* features = (const float*)d_in[0];
    const void*  edge     = d_in[1];
    const float* emb_W    = (const float*)d_in[2];
    const float* emb_b    = (const float*)d_in[3];
    const float* Wself    = (const float*)d_in[4];
    const float* Wneigh   = (const float*)d_in[5];
    const float* conv_b   = (const float*)d_in[6];
    const float* gamma    = (const float*)d_in[7];
    const float* beta     = (const float*)d_in[8];
    const float* W1       = (const float*)d_in[9];
    const float* b1       = (const float*)d_in[10];
    const float* W2       = (const float*)d_in[11];
    const float* b2       = (const float*)d_in[12];
    float* out = (float*)d_out;

    detect_dtype_kernel<<<1, 128>>>(edge);
    extract_edges_kernel<<<(2 * EE + 255) / 256, 256>>>(edge);
    zero_deg_kernel<<<(NN + 255) / 256, 256>>>();
    count_deg_kernel<<<(EE + 255) / 256, 256>>>();
    calc_invdeg_kernel<<<(NN + 255) / 256, 256>>>();
    embed_kernel<<<2048, 128>>>(features, emb_W, emb_b);  // h -> buf0

    int h = 0;  // current h buffer selector; msg buffer is h^1
    for (int i = 0; i < NL; i++) {
        zero_msg_stats_kernel<<<(NN * HD / 4 + 255) / 256, 256>>>(h ^ 1);
        scatter_kernel<<<(EE * 32 + 255) / 256, 256>>>(h);
        gemm_layer_kernel<<<(NN + BM - 1) / BM, 256>>>(
            h, Wself + (size_t)i * HD * HD, Wneigh + (size_t)i * HD * HD,
            conv_b + i * HD);                        // writes into h^1 + BN stats
        bn_finalize_kernel<<<1, HD>>>(gamma + i * HD, beta + i * HD);
        bn_apply_kernel<<<(NN * HD / 4 + 255) / 256, 256>>>(h ^ 1, i > 0);
        h ^= 1;
    }
    head_kernel<<<1024, 256>>>(h, W1, b1, W2, b2, out);
}

// round 6
// speedup vs baseline: 1.3559x; 1.0090x over previous
#include <cuda_runtime.h>
#include <mma.h>

using namespace nvcuda;

#define NN 100000
#define EE 600000
#define IND 12
#define HD  128
#define NL  3
#define BNEPS 1e-5f

// ---------------- device scratch (static, no allocation) ----------------
__device__ float g_buf0[NN * HD];
__device__ float g_buf1[NN * HD];
__device__ int   g_src[EE];
__device__ int   g_dst[EE];
__device__ int   g_adj[EE];          // CSR: src ids grouped by dst
__device__ int   g_rowptr[NN + 1];
__device__ int   g_cursor[NN];
__device__ int   g_deg[NN];
__device__ float g_invdeg[NN];
__device__ float g_sum[HD];
__device__ float g_sqsum[HD];
__device__ float g_scale[HD];
__device__ float g_shift[HD];
__device__ int   g_is64;

__device__ __forceinline__ float* selbuf(int s) { return s ? g_buf1 : g_buf0; }

// ---------------- dtype detection for edge_index (int32 vs int64) -------
__global__ void detect_dtype_kernel(const void* p) {
    const int* pi = (const int*)p;
    int nz = 0;
    for (int k = threadIdx.x; k < 256; k += blockDim.x)
        nz |= (pi[2 * k + 1] != 0);
    nz = __syncthreads_or(nz);
    if (threadIdx.x == 0) g_is64 = nz ? 0 : 1;
}

__global__ void extract_edges_kernel(const void* p) {
    int i = blockIdx.x * blockDim.x + threadIdx.x;
    if (i >= 2 * EE) return;
    int v;
    if (g_is64) v = (int)((const long long*)p)[i];
    else        v = ((const int*)p)[i];
    if (i < EE) g_src[i] = v;
    else        g_dst[i - EE] = v;
}

// ---------------- degree ----------------
__global__ void zero_deg_kernel() {
    int i = blockIdx.x * blockDim.x + threadIdx.x;
    if (i < NN) g_deg[i] = 0;
}
__global__ void count_deg_kernel() {
    int e = blockIdx.x * blockDim.x + threadIdx.x;
    if (e < EE) atomicAdd(&g_deg[g_dst[e]], 1);
}
// invdeg + one-time BN-sum init
__global__ void calc_invdeg_kernel() {
    int i = blockIdx.x * blockDim.x + threadIdx.x;
    if (i < NN) g_invdeg[i] = 1.0f / fmaxf((float)g_deg[i], 1.0f);
    if (i < HD) { g_sum[i] = 0.f; g_sqsum[i] = 0.f; }
}

// ---------------- CSR row pointers: single-block hierarchical scan ------
__global__ void rowptr_kernel() {   // <<<1, 1024>>>
    __shared__ int wsum[32];
    __shared__ int sbase;
    int tid = threadIdx.x, lane = tid & 31, wid = tid >> 5;
    if (tid == 0) { sbase = 0; g_rowptr[0] = 0; }
    __syncthreads();
    for (int c0 = 0; c0 < NN; c0 += 4096) {
        int i0 = c0 + tid * 4;
        int v0 = (i0 + 0 < NN) ? g_deg[i0 + 0] : 0;
        int v1 = (i0 + 1 < NN) ? g_deg[i0 + 1] : 0;
        int v2 = (i0 + 2 < NN) ? g_deg[i0 + 2] : 0;
        int v3 = (i0 + 3 < NN) ? g_deg[i0 + 3] : 0;
        int s = v0 + v1 + v2 + v3;
        int inc = s;
#pragma unroll
        for (int off = 1; off < 32; off <<= 1) {
            int t = __shfl_up_sync(0xffffffffu, inc, off);
            if (lane >= off) inc += t;
        }
        if (lane == 31) wsum[wid] = inc;
        __syncthreads();
        if (wid == 0) {
            int wi = wsum[lane];
#pragma unroll
            for (int off = 1; off < 32; off <<= 1) {
                int t = __shfl_up_sync(0xffffffffu, wi, off);
                if (lane >= off) wi += t;
            }
            wsum[lane] = wi;
        }
        __syncthreads();
        int excl = inc - s + (wid ? wsum[wid - 1] : 0) + sbase;
        int r = excl;
        if (i0 + 0 < NN) { r += v0; g_rowptr[i0 + 1] = r; }
        if (i0 + 1 < NN) { r += v1; g_rowptr[i0 + 2] = r; }
        if (i0 + 2 < NN) { r += v2; g_rowptr[i0 + 3] = r; }
        if (i0 + 3 < NN) { r += v3; g_rowptr[i0 + 4] = r; }
        __syncthreads();
        if (tid == 0) sbase += wsum[31];
        __syncthreads();
    }
}

__global__ void cursor_init_kernel() {
    int i = blockIdx.x * blockDim.x + threadIdx.x;
    if (i < NN) g_cursor[i] = g_rowptr[i];
}
__global__ void place_edges_kernel() {
    int e = blockIdx.x * blockDim.x + threadIdx.x;
    if (e >= EE) return;
    int d = g_dst[e];
    int pos = atomicAdd(&g_cursor[d], 1);
    g_adj[pos] = g_src[e];
}

// ---------------- embedding: h = F @ emb_W + emb_b  -> buf0 -------------
__global__ void embed_kernel(const float* __restrict__ F,
                             const float* __restrict__ W,
                             const float* __restrict__ b) {
    __shared__ float Ws[IND * HD];
    for (int i = threadIdx.x; i < IND * HD; i += blockDim.x) Ws[i] = W[i];
    __syncthreads();
    float* Hout = g_buf0;
    int c = threadIdx.x;  // 128 threads
    float bc = b[c];
    for (int n = blockIdx.x; n < NN; n += gridDim.x) {
        float acc = bc;
#pragma unroll
        for (int k = 0; k < IND; k++)
            acc += F[n * IND + k] * Ws[k * HD + c];
        Hout[n * HD + c] = acc;
    }
}

// ---------------- CSR gather: msg[n] = invdeg[n] * sum_{s in adj(n)} h[s]
// One warp per destination node. No atomics, no zeroing pass.
__global__ void gather_kernel(int hsel) {
    const float* __restrict__ h = selbuf(hsel);
    float* __restrict__ msg = selbuf(hsel ^ 1);
    int gid = blockIdx.x * blockDim.x + threadIdx.x;
    int node = gid >> 5;
    if (node >= NN) return;
    int lane = gid & 31;
    int beg = __ldg(&g_rowptr[node]);
    int end = __ldg(&g_rowptr[node + 1]);
    float4 acc = make_float4(0.f, 0.f, 0.f, 0.f);
    int j = beg;
    for (; j + 1 < end; j += 2) {
        int s0 = __ldg(&g_adj[j]);
        int s1 = __ldg(&g_adj[j + 1]);
        float4 a = __ldg((const float4*)(h + (size_t)s0 * HD) + lane);
        float4 b = __ldg((const float4*)(h + (size_t)s1 * HD) + lane);
        acc.x += a.x + b.x; acc.y += a.y + b.y;
        acc.z += a.z + b.z; acc.w += a.w + b.w;
    }
    if (j < end) {
        int s0 = __ldg(&g_adj[j]);
        float4 a = __ldg((const float4*)(h + (size_t)s0 * HD) + lane);
        acc.x += a.x; acc.y += a.y; acc.z += a.z; acc.w += a.w;
    }
    float sc = g_invdeg[node];
    acc.x *= sc; acc.y *= sc; acc.z *= sc; acc.w *= sc;
    ((float4*)(msg + (size_t)node * HD))[lane] = acc;
}

// ---------------- fused dual GEMM (tf32 tensor cores, in-place) --------
//   C = h @ Wself + msg @ Wneigh + bias,  C overwrites msg (pre-scaled).
//   BN column statistics fused into the epilogue.
//   tf32 rounding applied at smem store (once per element).
#define BM 128
#define BK 16
#define ALD (BK + 4)     // 20 floats = 80 B, x16 OK
#define BLD (HD + 4)     // 132 floats, x16 OK
#define WTLD 20          // 80 B, x16 OK
__global__ void __launch_bounds__(256)
gemm_layer_kernel(int hsel,
                  const float* __restrict__ Wsp,
                  const float* __restrict__ Wnp,
                  const float* __restrict__ bias) {
    __shared__ float As[BM * ALD];
    __shared__ float Bs[BK * BLD];
    __shared__ float wtile[8][16 * WTLD];
    __shared__ float colsum[HD], colsq[HD];

    const float* A1 = selbuf(hsel);
    float* Msg = selbuf(hsel ^ 1);
    float* C = Msg;  // in-place
    const int nrows = NN;
    int tid = threadIdx.x;
    int w = tid >> 5, lane = tid & 31;
    int wm = w & 3, wn = w >> 2;       // warp grid 4(M) x 2(N)
    int row0 = blockIdx.x * BM;

    if (tid < HD) { colsum[tid] = 0.f; colsq[tid] = 0.f; }

    wmma::fragment<wmma::accumulator, 16, 16, 8, float> acc[2][4];
#pragma unroll
    for (int i = 0; i < 2; i++)
#pragma unroll
        for (int j = 0; j < 4; j++) wmma::fill_fragment(acc[i][j], 0.f);

    for (int pass = 0; pass < 2; ++pass) {
        const float* A = pass ? Msg : A1;
        const float* W = pass ? Wnp : Wsp;
        for (int k0 = 0; k0 < HD; k0 += BK) {
            __syncthreads();
            // A tile: 128 rows x 16 cols (512 float4 loads / 256 threads)
#pragma unroll
            for (int q = 0; q < 2; q++) {
                int idx = tid * 2 + q;          // 0..511
                int m = idx >> 2;               // row in tile
                int kk = (idx & 3) * 4;         // col in tile
                int row = row0 + m;
                int rc = row < nrows ? row : nrows - 1;
                float4 v = __ldg((const float4*)(A + (size_t)rc * HD + k0 + kk));
                As[m * ALD + kk + 0] = wmma::__float_to_tf32(v.x);
                As[m * ALD + kk + 1] = wmma::__float_to_tf32(v.y);
                As[m * ALD + kk + 2] = wmma::__float_to_tf32(v.z);
                As[m * ALD + kk + 3] = wmma::__float_to_tf32(v.w);
            }
            // W tile: 16 rows x 128 cols
#pragma unroll
            for (int q = 0; q < 2; q++) {
                int idx = tid * 2 + q;
                int kk = idx >> 5;
                int c4 = idx & 31;
                float4 v = __ldg((const float4*)(W + (size_t)(k0 + kk) * HD + c4 * 4));
                Bs[kk * BLD + c4 * 4 + 0] = wmma::__float_to_tf32(v.x);
                Bs[kk * BLD + c4 * 4 + 1] = wmma::__float_to_tf32(v.y);
                Bs[kk * BLD + c4 * 4 + 2] = wmma::__float_to_tf32(v.z);
                Bs[kk * BLD + c4 * 4 + 3] = wmma::__float_to_tf32(v.w);
            }
            __syncthreads();
#pragma unroll
            for (int ks = 0; ks < BK; ks += 8) {
                wmma::fragment<wmma::matrix_a, 16, 16, 8, wmma::precision::tf32, wmma::row_major> af[2];
                wmma::fragment<wmma::matrix_b, 16, 16, 8, wmma::precision::tf32, wmma::row_major> bf[4];
#pragma unroll
                for (int i = 0; i < 2; i++)
                    wmma::load_matrix_sync(af[i], &As[(wm * 32 + i * 16) * ALD + ks], ALD);
#pragma unroll
                for (int j = 0; j < 4; j++)
                    wmma::load_matrix_sync(bf[j], &Bs[ks * BLD + wn * 64 + j * 16], BLD);
#pragma unroll
                for (int i = 0; i < 2; i++)
#pragma unroll
                    for (int j = 0; j < 4; j++)
                        wmma::mma_sync(acc[i][j], af[i], bf[j], acc[i][j]);
            }
        }
    }

    // Epilogue: bias add, bounds-checked store, fused BN column stats.
    float* wt = wtile[w];
    int cl = lane & 15;        // column within 16
    int rh = lane >> 4;        // row half (0/1)
#pragma unroll
    for (int i = 0; i < 2; i++) {
#pragma unroll
        for (int j = 0; j < 4; j++) {
            wmma::store_matrix_sync(wt, acc[i][j], WTLD, wmma::mem_row_major);
            __syncwarp();
            int gc = wn * 64 + j * 16 + cl;
            int rbase = row0 + wm * 32 + i * 16 + rh * 8;
            float bia = bias[gc];
            float s = 0.f, s2 = 0.f;
#pragma unroll
            for (int r = 0; r < 8; r++) {
                int gr = rbase + r;
                float v = wt[(rh * 8 + r) * WTLD + cl] + bia;
                if (gr < nrows) {
                    C[(size_t)gr * HD + gc] = v;
                    s += v;
                    s2 += v * v;
                }
            }
            s  += __shfl_down_sync(0xffffffffu, s, 16);
            s2 += __shfl_down_sync(0xffffffffu, s2, 16);
            if (lane < 16) {
                atomicAdd(&colsum[gc], s);
                atomicAdd(&colsq[gc], s2);
            }
            __syncwarp();
        }
    }
    __syncthreads();
    if (tid < HD) {
        atomicAdd(&g_sum[tid], colsum[tid]);
        atomicAdd(&g_sqsum[tid], colsq[tid]);
    }
}

// ---------------- BN finalize (+self-reset of sums for next layer) -----
__global__ void bn_finalize_kernel(const float* __restrict__ gamma,
                                   const float* __restrict__ beta) {
    int c = threadIdx.x;
    float mu = g_sum[c] * (1.0f / NN);
    float var = g_sqsum[c] * (1.0f / NN) - mu * mu;
    float r = rsqrtf(var + BNEPS);
    float a = gamma[c] * r;
    g_scale[c] = a;
    g_shift[c] = beta[c] - mu * a;
    g_sum[c] = 0.f;
    g_sqsum[c] = 0.f;
}

// ---------------- BN apply + ReLU + (residual) ----------------
__global__ void bn_apply_kernel(int sel, int addres) {
    float* X = selbuf(sel);
    const float* Res = selbuf(sel ^ 1);  // layer input = residual source
    int i = blockIdx.x * blockDim.x + threadIdx.x;
    int total4 = NN * HD / 4;
    if (i >= total4) return;
    int c = (i & 31) * 4;
    float4 v = ((float4*)X)[i];
    v.x = fmaxf(v.x * g_scale[c + 0] + g_shift[c + 0], 0.f);
    v.y = fmaxf(v.y * g_scale[c + 1] + g_shift[c + 1], 0.f);
    v.z = fmaxf(v.z * g_scale[c + 2] + g_shift[c + 2], 0.f);
    v.w = fmaxf(v.w * g_scale[c + 3] + g_shift[c + 3], 0.f);
    if (addres) {
        float4 r = ((const float4*)Res)[i];
        v.x += r.x; v.y += r.y; v.z += r.z; v.w += r.w;
    }
    ((float4*)X)[i] = v;
}

// ---------------- MLP head: out = relu(h@W1+b1)@W2+b2 ----------------
__global__ void head_kernel(int sel,
                            const float* __restrict__ W1,
                            const float* __restrict__ b1,
                            const float* __restrict__ W2,
                            const float* __restrict__ b2,
                            float* __restrict__ out) {
    const float* Hin = selbuf(sel);
    __shared__ float W1s[HD * 64];
    __shared__ float W2s[64 * 2];
    __shared__ float b1s[64];
    for (int i = threadIdx.x; i < HD * 64; i += blockDim.x) W1s[i] = W1[i];
    if (threadIdx.x < 128) W2s[threadIdx.x] = W2[threadIdx.x];
    if (threadIdx.x < 64) b1s[threadIdx.x] = b1[threadIdx.x];
    __syncthreads();
    int lane = threadIdx.x & 31;
    int w = threadIdx.x >> 5;
    int wpg = gridDim.x * (blockDim.x >> 5);
    float b20 = b2[0], b21 = b2[1];
    for (int n = blockIdx.x * (blockDim.x >> 5) + w; n < NN; n += wpg) {
        float4 h4 = __ldg((const float4*)(Hin + (size_t)n * HD) + lane);
        float hv[4] = {h4.x, h4.y, h4.z, h4.w};
        float a0 = b1s[lane], a1 = b1s[lane + 32];
#pragma unroll
        for (int k = 0; k < HD; k++) {
            float v = __shfl_sync(0xffffffffu, hv[k & 3], k >> 2);
            a0 += v * W1s[k * 64 + lane];
            a1 += v * W1s[k * 64 + lane + 32];
        }
        a0 = fmaxf(a0, 0.f);
        a1 = fmaxf(a1, 0.f);
        float o0 = a0 * W2s[lane * 2 + 0] + a1 * W2s[(lane + 32) * 2 + 0];
        float o1 = a0 * W2s[lane * 2 + 1] + a1 * W2s[(lane + 32) * 2 + 1];
#pragma unroll
        for (int off = 16; off; off >>= 1) {
            o0 += __shfl_xor_sync(0xffffffffu, o0, off);
            o1 += __shfl_xor_sync(0xffffffffu, o1, off);
        }
        if (lane == 0) {
            out[n * 2 + 0] = o0 + b20;
            out[n * 2 + 1] = o1 + b21;
        }
    }
}

// ---------------- launch (kernel launches ONLY) ----------------
extern "C" void kernel_launch(void* const* d_in, const int* in_sizes, int n_in,
                              void* d_out, int out_size) {
    const float* features = (const float*)d_in[0];
    const void*  edge     = d_in[1];
    const float* emb_W    = (const float*)d_in[2];
    const float* emb_b    = (const float*)d_in[3];
    const float* Wself    = (const float*)d_in[4];
    const float* Wneigh   = (const float*)d_in[5];
    const float* conv_b   = (const float*)d_in[6];
    const float* gamma    = (const float*)d_in[7];
    const float* beta     = (const float*)d_in[8];
    const float* W1       = (const float*)d_in[9];
    const float* b1       = (const float*)d_in[10];
    const float* W2       = (const float*)d_in[11];
    const float* b2       = (const float*)d_in[12];
    float* out = (float*)d_out;

    detect_dtype_kernel<<<1, 128>>>(edge);
    extract_edges_kernel<<<(2 * EE + 255) / 256, 256>>>(edge);
    zero_deg_kernel<<<(NN + 255) / 256, 256>>>();
    count_deg_kernel<<<(EE + 255) / 256, 256>>>();
    calc_invdeg_kernel<<<(NN + 255) / 256, 256>>>();
    rowptr_kernel<<<1, 1024>>>();
    cursor_init_kernel<<<(NN + 255) / 256, 256>>>();
    place_edges_kernel<<<(EE + 255) / 256, 256>>>();
    embed_kernel<<<2048, 128>>>(features, emb_W, emb_b);  // h -> buf0

    int h = 0;  // current h buffer selector; msg buffer is h^1
    for (int i = 0; i < NL; i++) {
        gather_kernel<<<(NN * 32 + 255) / 256, 256>>>(h);
        gemm_layer_kernel<<<(NN + BM - 1) / BM, 256>>>(
            h, Wself + (size_t)i * HD * HD, Wneigh + (size_t)i * HD * HD,
            conv_b + i * HD);                        // writes into h^1 + BN stats
        bn_finalize_kernel<<<1, HD>>>(gamma + i * HD, beta + i * HD);
        bn_apply_kernel<<<(NN * HD / 4 + 255) / 256, 256>>>(h ^ 1, i > 0);
        h ^= 1;
    }
    head_kernel<<<1024, 256>>>(h, W1, b1, W2, b2, out);
}

// round 8
// speedup vs baseline: 1.7303x; 1.2762x over previous
#include <cuda_runtime.h>
#include <mma.h>

using namespace nvcuda;

#define NN 100000
#define EE 600000
#define IND 12
#define HD  128
#define NL  3
#define BNEPS 1e-5f

// ---------------- device scratch (static, no allocation) ----------------
// NOTE: total static size must stay ~<=111 MB (GB300 fabric-init threshold,
// measured: 111 MB passes, 116 MB fails with cudaErrorSystemNotReady).
// msg12 (layer-1 12-dim gather output) is ALIASED into g_buf0, which is
// dead during layer 1 (first written by layer 2's gather).
__device__ float g_buf0[NN * HD];
__device__ float g_buf1[NN * HD];
__device__ int   g_src[EE];
__device__ int   g_dst[EE];
__device__ int   g_adj[EE];              // CSR: src ids grouped by dst
__device__ int   g_rowptr[NN + 1];
__device__ int   g_cursor[NN];
__device__ int   g_deg[NN];
__device__ float g_invdeg[NN];
__device__ float g_W1c[IND * HD];        // embW @ Wself[0]
__device__ float g_W2c[IND * HD];        // embW @ Wneigh[0]
__device__ float g_bias1[HD];            // emb_b @ Wself[0] + conv_b[0]
__device__ float g_biasd[HD];            // emb_b @ Wneigh[0]  (gated by deg>0)
__device__ float g_sum[HD];
__device__ float g_sqsum[HD];
__device__ float g_scale[HD];
__device__ float g_shift[HD];
__device__ int   g_is64;

__device__ __forceinline__ float* selbuf(int s) { return s ? g_buf1 : g_buf0; }

// ---------------- dtype detection for edge_index (int32 vs int64) -------
__global__ void detect_dtype_kernel(const void* p) {
    const int* pi = (const int*)p;
    int nz = 0;
    for (int k = threadIdx.x; k < 256; k += blockDim.x)
        nz |= (pi[2 * k + 1] != 0);
    nz = __syncthreads_or(nz);
    if (threadIdx.x == 0) g_is64 = nz ? 0 : 1;
}

// extract edges + zero degree array (independent work, one launch)
__global__ void extract_edges_kernel(const void* p) {
    int i = blockIdx.x * blockDim.x + threadIdx.x;
    if (i < NN) g_deg[i] = 0;
    if (i >= 2 * EE) return;
    int v;
    if (g_is64) v = (int)((const long long*)p)[i];
    else        v = ((const int*)p)[i];
    if (i < EE) g_src[i] = v;
    else        g_dst[i - EE] = v;
}

__global__ void count_deg_kernel() {
    int e = blockIdx.x * blockDim.x + threadIdx.x;
    if (e < EE) atomicAdd(&g_deg[g_dst[e]], 1);
}

// ---------------- layer-1 folded weights: W*c = embW @ W*[0] ------------
__global__ void prep_weights_kernel(const float* __restrict__ embW,
                                    const float* __restrict__ emb_b,
                                    const float* __restrict__ Ws,
                                    const float* __restrict__ Wn,
                                    const float* __restrict__ cb) {
    int c = threadIdx.x;            // 128
    int k = blockIdx.x;             // 0..12 (12 = bias block)
    if (k < IND) {
        float a1 = 0.f, a2 = 0.f;
        for (int j = 0; j < HD; j++) {
            float e = __ldg(&embW[k * HD + j]);
            a1 += e * __ldg(&Ws[j * HD + c]);
            a2 += e * __ldg(&Wn[j * HD + c]);
        }
        g_W1c[k * HD + c] = a1;
        g_W2c[k * HD + c] = a2;
    } else {
        float b1 = 0.f, b2 = 0.f;
        for (int j = 0; j < HD; j++) {
            float e = __ldg(&emb_b[j]);
            b1 += e * __ldg(&Ws[j * HD + c]);
            b2 += e * __ldg(&Wn[j * HD + c]);
        }
        g_bias1[c] = b1 + __ldg(&cb[c]);
        g_biasd[c] = b2;
    }
}

// invdeg + one-time BN-sum init
__global__ void calc_invdeg_kernel() {
    int i = blockIdx.x * blockDim.x + threadIdx.x;
    if (i < NN) g_invdeg[i] = 1.0f / fmaxf((float)g_deg[i], 1.0f);
    if (i < HD) { g_sum[i] = 0.f; g_sqsum[i] = 0.f; }
}

// ---------------- CSR row pointers + cursor: single-block scan ----------
__global__ void rowptr_kernel() {   // <<<1, 1024>>>
    __shared__ int wsum[32];
    __shared__ int sbase;
    int tid = threadIdx.x, lane = tid & 31, wid = tid >> 5;
    if (tid == 0) { sbase = 0; g_rowptr[0] = 0; }
    __syncthreads();
    for (int c0 = 0; c0 < NN; c0 += 4096) {
        int i0 = c0 + tid * 4;
        int v0 = (i0 + 0 < NN) ? g_deg[i0 + 0] : 0;
        int v1 = (i0 + 1 < NN) ? g_deg[i0 + 1] : 0;
        int v2 = (i0 + 2 < NN) ? g_deg[i0 + 2] : 0;
        int v3 = (i0 + 3 < NN) ? g_deg[i0 + 3] : 0;
        int s = v0 + v1 + v2 + v3;
        int inc = s;
#pragma unroll
        for (int off = 1; off < 32; off <<= 1) {
            int t = __shfl_up_sync(0xffffffffu, inc, off);
            if (lane >= off) inc += t;
        }
        if (lane == 31) wsum[wid] = inc;
        __syncthreads();
        if (wid == 0) {
            int wi = wsum[lane];
#pragma unroll
            for (int off = 1; off < 32; off <<= 1) {
                int t = __shfl_up_sync(0xffffffffu, wi, off);
                if (lane >= off) wi += t;
            }
            wsum[lane] = wi;
        }
        __syncthreads();
        int r = inc - s + (wid ? wsum[wid - 1] : 0) + sbase;
        if (i0 + 0 < NN) { g_cursor[i0 + 0] = r; r += v0; g_rowptr[i0 + 1] = r; }
        if (i0 + 1 < NN) { g_cursor[i0 + 1] = r; r += v1; g_rowptr[i0 + 2] = r; }
        if (i0 + 2 < NN) { g_cursor[i0 + 2] = r; r += v2; g_rowptr[i0 + 3] = r; }
        if (i0 + 3 < NN) { g_cursor[i0 + 3] = r; r += v3; g_rowptr[i0 + 4] = r; }
        __syncthreads();
        if (tid == 0) sbase += wsum[31];
        __syncthreads();
    }
}

__global__ void place_edges_kernel() {
    int e = blockIdx.x * blockDim.x + threadIdx.x;
    if (e >= EE) return;
    int d = g_dst[e];
    int pos = atomicAdd(&g_cursor[d], 1);
    g_adj[pos] = g_src[e];
}

// ---------------- layer-1 gather in 12-dim feature space ---------------
// msg12[n] = invdeg[n] * sum_{s in adj(n)} F[s]  -> stored in g_buf0 alias
__global__ void gather12_kernel(const float* __restrict__ F) {
    float* __restrict__ msg12 = g_buf0;   // alias: buf0 dead during layer 1
    int gid = blockIdx.x * blockDim.x + threadIdx.x;
    int node = gid >> 2, ch = gid & 3;
    if (node >= NN || ch >= 3) return;
    int beg = __ldg(&g_rowptr[node]);
    int end = __ldg(&g_rowptr[node + 1]);
    float4 acc = make_float4(0.f, 0.f, 0.f, 0.f);
    for (int j = beg; j < end; j++) {
        int s = __ldg(&g_adj[j]);
        float4 v = __ldg((const float4*)(F + (size_t)s * IND) + ch);
        acc.x += v.x; acc.y += v.y; acc.z += v.z; acc.w += v.w;
    }
    float sc = g_invdeg[node];
    acc.x *= sc; acc.y *= sc; acc.z *= sc; acc.w *= sc;
    *(float4*)(msg12 + (size_t)node * IND + ch * 4) = acc;
}

// ---------------- layer-1 GEMM (K=12, fp32 FFMA) -> buf1 raw -----------
// C = F @ W1c + msg12 @ W2c + bias1 + (deg>0)*biasd ; fused BN stats.
#define G12NB 8
__global__ void __launch_bounds__(128)
gemm12_kernel(const float* __restrict__ F) {
    const float* __restrict__ msg12 = g_buf0;  // alias
    __shared__ float W1s[IND * HD], W2s[IND * HD];
    __shared__ float Fs[G12NB][IND], Ms[G12NB][IND];
    int c = threadIdx.x;
    for (int i = c; i < IND * HD; i += 128) { W1s[i] = g_W1c[i]; W2s[i] = g_W2c[i]; }
    float bfx = g_bias1[c], bdg = g_biasd[c];
    int nrow_off = c / IND, kk = c % IND;   // for the 96 loader threads
    float s = 0.f, s2 = 0.f;
    float* C = g_buf1;
    for (int base = blockIdx.x * G12NB; base < NN; base += gridDim.x * G12NB) {
        __syncthreads();
        if (c < 8 * IND) {
            int n = base + nrow_off;
            Fs[nrow_off][kk] = (n < NN) ? __ldg(&F[(size_t)n * IND + kk]) : 0.f;
            Ms[nrow_off][kk] = (n < NN) ? msg12[(size_t)n * IND + kk] : 0.f;
        }
        __syncthreads();
#pragma unroll
        for (int r = 0; r < G12NB; r++) {
            int n = base + r;
            if (n >= NN) break;
            float acc = bfx + (__ldg(&g_deg[n]) ? bdg : 0.f);
#pragma unroll
            for (int k = 0; k < IND; k++)
                acc += Fs[r][k] * W1s[k * HD + c] + Ms[r][k] * W2s[k * HD + c];
            C[(size_t)n * HD + c] = acc;
            s += acc; s2 += acc * acc;
        }
    }
    atomicAdd(&g_sum[c], s);
    atomicAdd(&g_sqsum[c], s2);
}

// ---------------- CSR gather (128-dim, layers 2..L) --------------------
__global__ void gather_kernel(int hsel) {
    const float* __restrict__ h = selbuf(hsel);
    float* __restrict__ msg = selbuf(hsel ^ 1);
    int gid = blockIdx.x * blockDim.x + threadIdx.x;
    int node = gid >> 5;
    if (node >= NN) return;
    int lane = gid & 31;
    int beg = __ldg(&g_rowptr[node]);
    int end = __ldg(&g_rowptr[node + 1]);
    float4 acc = make_float4(0.f, 0.f, 0.f, 0.f);
    int j = beg;
    for (; j + 1 < end; j += 2) {
        int s0 = __ldg(&g_adj[j]);
        int s1 = __ldg(&g_adj[j + 1]);
        float4 a = __ldg((const float4*)(h + (size_t)s0 * HD) + lane);
        float4 b = __ldg((const float4*)(h + (size_t)s1 * HD) + lane);
        acc.x += a.x + b.x; acc.y += a.y + b.y;
        acc.z += a.z + b.z; acc.w += a.w + b.w;
    }
    if (j < end) {
        int s0 = __ldg(&g_adj[j]);
        float4 a = __ldg((const float4*)(h + (size_t)s0 * HD) + lane);
        acc.x += a.x; acc.y += a.y; acc.z += a.z; acc.w += a.w;
    }
    float sc = g_invdeg[node];
    acc.x *= sc; acc.y *= sc; acc.z *= sc; acc.w *= sc;
    ((float4*)(msg + (size_t)node * HD))[lane] = acc;
}

// ---------------- fused dual GEMM (tf32 tensor cores, in-place) --------
#define BM 128
#define BK 16
#define ALD (BK + 4)
#define BLD (HD + 4)
#define WTLD 20
__global__ void __launch_bounds__(256)
gemm_layer_kernel(int hsel,
                  const float* __restrict__ Wsp,
                  const float* __restrict__ Wnp,
                  const float* __restrict__ bias) {
    __shared__ float As[BM * ALD];
    __shared__ float Bs[BK * BLD];
    __shared__ float wtile[8][16 * WTLD];
    __shared__ float colsum[HD], colsq[HD];

    const float* A1 = selbuf(hsel);
    float* Msg = selbuf(hsel ^ 1);
    float* C = Msg;  // in-place
    const int nrows = NN;
    int tid = threadIdx.x;
    int w = tid >> 5, lane = tid & 31;
    int wm = w & 3, wn = w >> 2;
    int row0 = blockIdx.x * BM;

    if (tid < HD) { colsum[tid] = 0.f; colsq[tid] = 0.f; }

    wmma::fragment<wmma::accumulator, 16, 16, 8, float> acc[2][4];
#pragma unroll
    for (int i = 0; i < 2; i++)
#pragma unroll
        for (int j = 0; j < 4; j++) wmma::fill_fragment(acc[i][j], 0.f);

    for (int pass = 0; pass < 2; ++pass) {
        const float* A = pass ? Msg : A1;
        const float* W = pass ? Wnp : Wsp;
        for (int k0 = 0; k0 < HD; k0 += BK) {
            __syncthreads();
#pragma unroll
            for (int q = 0; q < 2; q++) {
                int idx = tid * 2 + q;
                int m = idx >> 2;
                int kk = (idx & 3) * 4;
                int row = row0 + m;
                int rc = row < nrows ? row : nrows - 1;
                float4 v = __ldg((const float4*)(A + (size_t)rc * HD + k0 + kk));
                As[m * ALD + kk + 0] = wmma::__float_to_tf32(v.x);
                As[m * ALD + kk + 1] = wmma::__float_to_tf32(v.y);
                As[m * ALD + kk + 2] = wmma::__float_to_tf32(v.z);
                As[m * ALD + kk + 3] = wmma::__float_to_tf32(v.w);
            }
#pragma unroll
            for (int q = 0; q < 2; q++) {
                int idx = tid * 2 + q;
                int kk = idx >> 5;
                int c4 = idx & 31;
                float4 v = __ldg((const float4*)(W + (size_t)(k0 + kk) * HD + c4 * 4));
                Bs[kk * BLD + c4 * 4 + 0] = wmma::__float_to_tf32(v.x);
                Bs[kk * BLD + c4 * 4 + 1] = wmma::__float_to_tf32(v.y);
                Bs[kk * BLD + c4 * 4 + 2] = wmma::__float_to_tf32(v.z);
                Bs[kk * BLD + c4 * 4 + 3] = wmma::__float_to_tf32(v.w);
            }
            __syncthreads();
#pragma unroll
            for (int ks = 0; ks < BK; ks += 8) {
                wmma::fragment<wmma::matrix_a, 16, 16, 8, wmma::precision::tf32, wmma::row_major> af[2];
                wmma::fragment<wmma::matrix_b, 16, 16, 8, wmma::precision::tf32, wmma::row_major> bf[4];
#pragma unroll
                for (int i = 0; i < 2; i++)
                    wmma::load_matrix_sync(af[i], &As[(wm * 32 + i * 16) * ALD + ks], ALD);
#pragma unroll
                for (int j = 0; j < 4; j++)
                    wmma::load_matrix_sync(bf[j], &Bs[ks * BLD + wn * 64 + j * 16], BLD);
#pragma unroll
                for (int i = 0; i < 2; i++)
#pragma unroll
                    for (int j = 0; j < 4; j++)
                        wmma::mma_sync(acc[i][j], af[i], bf[j], acc[i][j]);
            }
        }
    }

    float* wt = wtile[w];
    int cl = lane & 15;
    int rh = lane >> 4;
#pragma unroll
    for (int i = 0; i < 2; i++) {
#pragma unroll
        for (int j = 0; j < 4; j++) {
            wmma::store_matrix_sync(wt, acc[i][j], WTLD, wmma::mem_row_major);
            __syncwarp();
            int gc = wn * 64 + j * 16 + cl;
            int rbase = row0 + wm * 32 + i * 16 + rh * 8;
            float bia = bias[gc];
            float s = 0.f, s2 = 0.f;
#pragma unroll
            for (int r = 0; r < 8; r++) {
                int gr = rbase + r;
                float v = wt[(rh * 8 + r) * WTLD + cl] + bia;
                if (gr < nrows) {
                    C[(size_t)gr * HD + gc] = v;
                    s += v;
                    s2 += v * v;
                }
            }
            s  += __shfl_down_sync(0xffffffffu, s, 16);
            s2 += __shfl_down_sync(0xffffffffu, s2, 16);
            if (lane < 16) {
                atomicAdd(&colsum[gc], s);
                atomicAdd(&colsq[gc], s2);
            }
            __syncwarp();
        }
    }
    __syncthreads();
    if (tid < HD) {
        atomicAdd(&g_sum[tid], colsum[tid]);
        atomicAdd(&g_sqsum[tid], colsq[tid]);
    }
}

// ---------------- BN finalize (+self-reset of sums) --------------------
__global__ void bn_finalize_kernel(const float* __restrict__ gamma,
                                   const float* __restrict__ beta) {
    int c = threadIdx.x;
    float mu = g_sum[c] * (1.0f / NN);
    float var = g_sqsum[c] * (1.0f / NN) - mu * mu;
    float r = rsqrtf(var + BNEPS);
    float a = gamma[c] * r;
    g_scale[c] = a;
    g_shift[c] = beta[c] - mu * a;
    g_sum[c] = 0.f;
    g_sqsum[c] = 0.f;
}

// ---------------- BN apply + ReLU + (residual) ----------------
__global__ void bn_apply_kernel(int sel, int addres) {
    float* X = selbuf(sel);
    const float* Res = selbuf(sel ^ 1);
    int i = blockIdx.x * blockDim.x + threadIdx.x;
    int total4 = NN * HD / 4;
    if (i >= total4) return;
    int c = (i & 31) * 4;
    float4 v = ((float4*)X)[i];
    v.x = fmaxf(v.x * g_scale[c + 0] + g_shift[c + 0], 0.f);
    v.y = fmaxf(v.y * g_scale[c + 1] + g_shift[c + 1], 0.f);
    v.z = fmaxf(v.z * g_scale[c + 2] + g_shift[c + 2], 0.f);
    v.w = fmaxf(v.w * g_scale[c + 3] + g_shift[c + 3], 0.f);
    if (addres) {
        float4 r = ((const float4*)Res)[i];
        v.x += r.x; v.y += r.y; v.z += r.z; v.w += r.w;
    }
    ((float4*)X)[i] = v;
}

// ---------------- head with fused final BN+ReLU+residual ---------------
// h = relu(scale*raw+shift) + res ; out = relu(h@W1+b1)@W2+b2
__global__ void head_kernel(int rawsel,
                            const float* __restrict__ W1,
                            const float* __restrict__ b1,
                            const float* __restrict__ W2,
                            const float* __restrict__ b2,
                            float* __restrict__ out) {
    const float* Raw = selbuf(rawsel);
    const float* Res = selbuf(rawsel ^ 1);
    __shared__ float W1s[HD * 64];
    __shared__ float W2s[64 * 2];
    __shared__ float b1s[64];
    __shared__ float scs[HD], shs[HD];
    for (int i = threadIdx.x; i < HD * 64; i += blockDim.x) W1s[i] = W1[i];
    if (threadIdx.x < 128) {
        W2s[threadIdx.x] = W2[threadIdx.x];
        scs[threadIdx.x] = g_scale[threadIdx.x];
        shs[threadIdx.x] = g_shift[threadIdx.x];
    }
    if (threadIdx.x < 64) b1s[threadIdx.x] = b1[threadIdx.x];
    __syncthreads();
    int lane = threadIdx.x & 31;
    int w = threadIdx.x >> 5;
    int wpg = gridDim.x * (blockDim.x >> 5);
    float b20 = b2[0], b21 = b2[1];
    int c0 = lane * 4;
    float sc0 = scs[c0], sc1 = scs[c0 + 1], sc2 = scs[c0 + 2], sc3 = scs[c0 + 3];
    float sh0 = shs[c0], sh1 = shs[c0 + 1], sh2 = shs[c0 + 2], sh3 = shs[c0 + 3];
    for (int n = blockIdx.x * (blockDim.x >> 5) + w; n < NN; n += wpg) {
        float4 h4 = __ldg((const float4*)(Raw + (size_t)n * HD) + lane);
        float4 r4 = __ldg((const float4*)(Res + (size_t)n * HD) + lane);
        float hv[4];
        hv[0] = fmaxf(h4.x * sc0 + sh0, 0.f) + r4.x;
        hv[1] = fmaxf(h4.y * sc1 + sh1, 0.f) + r4.y;
        hv[2] = fmaxf(h4.z * sc2 + sh2, 0.f) + r4.z;
        hv[3] = fmaxf(h4.w * sc3 + sh3, 0.f) + r4.w;
        float a0 = b1s[lane], a1 = b1s[lane + 32];
#pragma unroll
        for (int k = 0; k < HD; k++) {
            float v = __shfl_sync(0xffffffffu, hv[k & 3], k >> 2);
            a0 += v * W1s[k * 64 + lane];
            a1 += v * W1s[k * 64 + lane + 32];
        }
        a0 = fmaxf(a0, 0.f);
        a1 = fmaxf(a1, 0.f);
        float o0 = a0 * W2s[lane * 2 + 0] + a1 * W2s[(lane + 32) * 2 + 0];
        float o1 = a0 * W2s[lane * 2 + 1] + a1 * W2s[(lane + 32) * 2 + 1];
#pragma unroll
        for (int off = 16; off; off >>= 1) {
            o0 += __shfl_xor_sync(0xffffffffu, o0, off);
            o1 += __shfl_xor_sync(0xffffffffu, o1, off);
        }
        if (lane == 0) {
            out[n * 2 + 0] = o0 + b20;
            out[n * 2 + 1] = o1 + b21;
        }
    }
}

// ---------------- launch (kernel launches ONLY) ----------------
extern "C" void kernel_launch(void* const* d_in, const int* in_sizes, int n_in,
                              void* d_out, int out_size) {
    const float* features = (const float*)d_in[0];
    const void*  edge     = d_in[1];
    const float* emb_W    = (const float*)d_in[2];
    const float* emb_b    = (const float*)d_in[3];
    const float* Wself    = (const float*)d_in[4];
    const float* Wneigh   = (const float*)d_in[5];
    const float* conv_b   = (const float*)d_in[6];
    const float* gamma    = (const float*)d_in[7];
    const float* beta     = (const float*)d_in[8];
    const float* W1       = (const float*)d_in[9];
    const float* b1       = (const float*)d_in[10];
    const float* W2       = (const float*)d_in[11];
    const float* b2       = (const float*)d_in[12];
    float* out = (float*)d_out;

    detect_dtype_kernel<<<1, 128>>>(edge);
    extract_edges_kernel<<<(2 * EE + 255) / 256, 256>>>(edge);
    count_deg_kernel<<<(EE + 255) / 256, 256>>>();
    prep_weights_kernel<<<IND + 1, 128>>>(emb_W, emb_b, Wself, Wneigh, conv_b);
    calc_invdeg_kernel<<<(NN + 255) / 256, 256>>>();
    rowptr_kernel<<<1, 1024>>>();
    place_edges_kernel<<<(EE + 255) / 256, 256>>>();

    // ---- layer 1 in 12-dim space (embed folded into weights) ----
    gather12_kernel<<<(NN * 4 + 255) / 256, 256>>>(features);   // msg12 -> buf0 alias
    gemm12_kernel<<<1024, 128>>>(features);            // -> buf1 raw + stats
    bn_finalize_kernel<<<1, HD>>>(gamma, beta);
    bn_apply_kernel<<<(NN * HD / 4 + 255) / 256, 256>>>(1, 0);  // buf1 = h1

    // ---- layer 2 ----
    gather_kernel<<<(NN * 32 + 255) / 256, 256>>>(1);           // buf1 -> buf0
    gemm_layer_kernel<<<(NN + BM - 1) / BM, 256>>>(
        1, Wself + (size_t)1 * HD * HD, Wneigh + (size_t)1 * HD * HD,
        conv_b + 1 * HD);                                        // -> buf0 raw
    bn_finalize_kernel<<<1, HD>>>(gamma + 1 * HD, beta + 1 * HD);
    bn_apply_kernel<<<(NN * HD / 4 + 255) / 256, 256>>>(0, 1);  // buf0 = h2

    // ---- layer 3 (final BN+ReLU+residual fused into head) ----
    gather_kernel<<<(NN * 32 + 255) / 256, 256>>>(0);           // buf0 -> buf1
    gemm_layer_kernel<<<(NN + BM - 1) / BM, 256>>>(
        0, Wself + (size_t)2 * HD * HD, Wneigh + (size_t)2 * HD * HD,
        conv_b + 2 * HD);                                        // -> buf1 raw
    bn_finalize_kernel<<<1, HD>>>(gamma + 2 * HD, beta + 2 * HD);
    head_kernel<<<1024, 256>>>(1, W1, b1, W2, b2, out);          // raw=buf1, res=buf0
}